// round 9
// baseline (speedup 1.0000x reference)
#include <cuda_runtime.h>
#include <cuda_bf16.h>

// Problem constants
#define B_    8
#define H_    256
#define P_    225          // H - KER + 1
#define KER_  32
#define HALF_ 16
#define K_    2
#define CDA_  64
#define NBC_  16           // B * 2 classes
#define NRB_  15           // row-slabs per map (15 output rows each)
#define NCH_  8            // 32-col chunks per map row
#define RS_   228          // smem rowsum stride (pad 225 -> 228, 16B aligned)

// Output section offsets (floats)
#define OFF_CLS   0
#define OFF_FEAT  65536
#define OFF_VALS  2162688
#define OFF_PES   2162720
#define OFF_TRUE  2195488
#define OFF_OXY   2228256

// Scratch
__device__ float g_pooled[NBC_ * P_ * P_];
__device__ float g_cval[NBC_ * NRB_ * NCH_];   // per (map, slab, col-chunk) partial
__device__ int   g_cidx[NBC_ * NRB_ * NCH_];
__device__ int   g_selpx[NBC_ * K_];
__device__ int   g_selpy[NBC_ * K_];
__device__ unsigned g_tick[NBC_];              // per-bc completion tickets (self-reset)

// Warp argmax combine: max value, lowest flat index on ties.
__device__ __forceinline__ void warp_argmax(float& bv, int& bix) {
#pragma unroll
    for (int o = 16; o > 0; o >>= 1) {
        float ov = __shfl_xor_sync(0xffffffffu, bv, o);
        int   oi = __shfl_xor_sync(0xffffffffu, bix, o);
        if (ov > bv || (ov == bv && oi < bix)) { bv = ov; bix = oi; }
    }
}

// ===========================================================================
// K1: per (bc, slab): softmax -> horizontal window (register scan) -> smem
// rowsums -> vertical slide -> pooled + partials; last slab block per bc
// (atomic ticket) runs greedy top-2 selection for that bc.
// grid (16, 15), 256 threads.
// ===========================================================================
__global__ void __launch_bounds__(256, 2)
k_poolsel(const float* __restrict__ infeat, float* __restrict__ out) {
    __shared__ float s_rs[46 * RS_];   // 46 input-window rows of rowsums
    __shared__ float sv[256];
    __shared__ int   si[256];
    __shared__ unsigned s_isLast;

    const int tid  = threadIdx.x;
    const int lane = tid & 31;
    const int warp = tid >> 5;
    const int bc   = blockIdx.x;       // b*2 + c
    const int slab = blockIdx.y;       // 0..14
    const int b = bc >> 1;
    const int c = bc & 1;
    const int y0 = slab * 15;          // first output row; inputs y0..y0+45

    const float* base_c = infeat + ((long)(b * 2 + c)       * H_) * H_;
    const float* base_o = infeat + ((long)(b * 2 + (1 - c)) * H_) * H_;

    // ---- horizontal: each warp processes rows warp, warp+8, ... of the 46 ----
    for (int row = warp; row < 46; row += 8) {
        int y = y0 + row;
        const float4* pc = (const float4*)(base_c + y * H_ + 8 * lane);
        const float4* po = (const float4*)(base_o + y * H_ + 8 * lane);
        float4 c0 = pc[0], c1 = pc[1];
        float4 o0 = po[0], o1 = po[1];

        // softmax over 2 channels: p_c = 1 / (1 + exp(x_other - x_c))
        float p[8];
        p[0] = 1.0f / (1.0f + __expf(o0.x - c0.x));
        p[1] = 1.0f / (1.0f + __expf(o0.y - c0.y));
        p[2] = 1.0f / (1.0f + __expf(o0.z - c0.z));
        p[3] = 1.0f / (1.0f + __expf(o0.w - c0.w));
        p[4] = 1.0f / (1.0f + __expf(o1.x - c1.x));
        p[5] = 1.0f / (1.0f + __expf(o1.y - c1.y));
        p[6] = 1.0f / (1.0f + __expf(o1.z - c1.z));
        p[7] = 1.0f / (1.0f + __expf(o1.w - c1.w));

        // local inclusive scan of 8
        float A[8];
        A[0] = p[0];
#pragma unroll
        for (int j = 1; j < 8; j++) A[j] = A[j - 1] + p[j];
        float tot = A[7];
        // warp inclusive scan of lane totals -> exclusive base
        float incl = tot;
#pragma unroll
        for (int o = 1; o < 32; o <<= 1) {
            float t = __shfl_up_sync(0xffffffffu, incl, o);
            if (lane >= o) incl += t;
        }
        float excl = incl - tot;
#pragma unroll
        for (int j = 0; j < 8; j++) A[j] += excl;   // global inclusive scan

        // window(x) = S[x+31] - S[x-1]
        float up7 = __shfl_up_sync(0xffffffffu, A[7], 1);     // S[8l-1]
        float d3  = __shfl_down_sync(0xffffffffu, A[7], 3);   // S[8l+31]
        float d4[7];
#pragma unroll
        for (int j = 0; j < 7; j++)
            d4[j] = __shfl_down_sync(0xffffffffu, A[j], 4);   // S[8(l+4)+j]

        float w[8];
        w[0] = d3 - (lane ? up7 : 0.0f);
#pragma unroll
        for (int r = 1; r < 8; r++) w[r] = d4[r - 1] - A[r - 1];

        // lane l owns outputs x = 8l..8l+7; valid x < 225
        float* dst = s_rs + row * RS_ + 8 * lane;
        if (lane <= 27) {
            *(float4*)(dst)     = make_float4(w[0], w[1], w[2], w[3]);
            *(float4*)(dst + 4) = make_float4(w[4], w[5], w[6], w[7]);
        } else if (lane == 28) {   // only x=224 real; 225..227 land in pad
            *(float4*)(dst)     = make_float4(w[0], w[1], w[2], w[3]);
        }
    }
    __syncthreads();

    // ---- vertical: sliding 32-window down smem rowsums ----
    float* outp = g_pooled + bc * P_ * P_;
    float best = -1e30f;
    int bi = 0x7fffffff;
    if (tid < P_) {
        float s = 0.0f;
#pragma unroll
        for (int i = 0; i < KER_; i++) s += s_rs[i * RS_ + tid];
        float v = s * (1.0f / 1024.0f);
        outp[y0 * P_ + tid] = v;
        best = v; bi = y0 * P_ + tid;
#pragma unroll
        for (int q = 1; q < 15; q++) {
            s += s_rs[(q + 31) * RS_ + tid] - s_rs[(q - 1) * RS_ + tid];
            v = s * (1.0f / 1024.0f);
            outp[(y0 + q) * P_ + tid] = v;
            if (v > best) { best = v; bi = (y0 + q) * P_ + tid; }
        }
    }
    warp_argmax(best, bi);           // warp w = cols [32w, 32w+32)
    if (lane == 0) {
        g_cval[(bc * NRB_ + slab) * NCH_ + warp] = best;
        g_cidx[(bc * NRB_ + slab) * NCH_ + warp] = bi;
    }

    // ---- per-bc ticket: last of 15 slab blocks does selection ----
    __threadfence();
    __syncthreads();
    if (tid == 0) {
        unsigned t = atomicAdd(&g_tick[bc], 1u);
        s_isLast = (t == NRB_ - 1) ? 1u : 0u;
    }
    __syncthreads();
    if (!s_isLast) return;
    __threadfence();

    const float* pm = g_pooled + bc * P_ * P_;

    // pass 1: reduce 120 chunk partials
    best = -1e30f; bi = 0x7fffffff;
    if (tid < NRB_ * NCH_) {
        best = g_cval[bc * NRB_ * NCH_ + tid];
        bi   = g_cidx[bc * NRB_ * NCH_ + tid];
    }
    sv[tid] = best; si[tid] = bi;
    __syncthreads();
    for (int s = 128; s > 0; s >>= 1) {
        if (tid < s) {
            float ov = sv[tid + s];
            int   oi = si[tid + s];
            if (ov > sv[tid] || (ov == sv[tid] && oi < si[tid])) {
                sv[tid] = ov; si[tid] = oi;
            }
        }
        __syncthreads();
    }
    int idx0 = si[0];
    float val0 = sv[0];
    int py0 = idx0 / P_;
    int px0 = idx0 - py0 * P_;
    __syncthreads();

    // pass 2: untouched partials + MLP-batched rescan of touched region
    int lo  = max(0, py0 - HALF_), hi  = min(P_, py0 + HALF_);
    int clo = max(0, px0 - HALF_), chi = min(P_, px0 + HALF_);
    int rblo = lo / 15, rbhi = (hi - 1) / 15;
    int cblo = clo / 32, cbhi = (chi - 1) / 32;

    best = -1e30f; bi = 0x7fffffff;
    if (tid < NRB_ * NCH_) {
        int s = tid >> 3, cc = tid & 7;
        if (s < rblo || s > rbhi || cc < cblo || cc > cbhi) {
            best = g_cval[bc * NRB_ * NCH_ + tid];
            bi   = g_cidx[bc * NRB_ * NCH_ + tid];
        }
    }
    int r0 = rblo * 15, r1 = min(P_, (rbhi + 1) * 15);
    int c0 = cblo * 32, c1 = min(P_, (cbhi + 1) * 32);
    int W = c1 - c0;
    int n = (r1 - r0) * W;                 // <= 3840
    for (int i0 = tid; i0 < n; i0 += 256 * 8) {
#pragma unroll
        for (int u = 0; u < 8; u++) {
            int i = i0 + u * 256;
            if (i < n) {
                int rr = i / W;
                int col = c0 + (i - rr * W);
                int row = r0 + rr;
                int idx = row * P_ + col;
                float v = pm[idx];
                if (row >= lo && row < hi && col >= clo && col < chi) v = 0.0f;
                if (v > best || (v == best && idx < bi)) { best = v; bi = idx; }
            }
        }
    }
    sv[tid] = best; si[tid] = bi;
    __syncthreads();
    for (int s = 128; s > 0; s >>= 1) {
        if (tid < s) {
            float ov = sv[tid + s];
            int   oi = si[tid + s];
            if (ov > sv[tid] || (ov == sv[tid] && oi < si[tid])) {
                sv[tid] = ov; si[tid] = oi;
            }
        }
        __syncthreads();
    }

    if (tid == 0) {
        int idx1 = si[0];
        float val1 = sv[0];
        int py1 = idx1 / P_;
        int px1 = idx1 - py1 * P_;

        int pxs[K_] = {px0, px1};
        int pys[K_] = {py0, py1};
        float vals[K_] = {val0, val1};
#pragma unroll
        for (int j = 0; j < K_; j++) {
            g_selpx[bc * K_ + j] = pxs[j];
            g_selpy[bc * K_ + j] = pys[j];
            out[OFF_VALS + (c * K_ + j) * B_ + b] = vals[j];
            int o = OFF_OXY + ((c * K_ + j) * B_ + b) * 4;
            out[o + 0] = (float)pxs[j];
            out[o + 1] = (float)(pxs[j] + KER_ - 1);
            out[o + 2] = (float)pys[j];
            out[o + 3] = (float)(pys[j] + KER_ - 1);
        }
        g_tick[bc] = 0;                 // reset for next launch
    }
}

// ===========================================================================
// K2: patch gather. 4 patches/block, 16 consecutive floats/thread:
// 16 independent scalar LDG (MLP 16) + 4 coalesced STG.128.
// grid 544, 256 threads.
// ===========================================================================
__global__ void k_extract(const float* __restrict__ infeat,
                          const float* __restrict__ pesudo,
                          const float* __restrict__ labelT,
                          const float* __restrict__ feat,
                          float* __restrict__ out) {
    int p = blockIdx.x * 4 + (threadIdx.x >> 6);
    int t64 = threadIdx.x & 63;

    const float* src;
    int Csrc, ch, c, j, b;
    long base;

    if (p < 64) {
        int t = p;
        ch = t & 1;  t >>= 1;
        b  = t & 7;  t >>= 3;
        j  = t & 1;  t >>= 1;
        c  = t;
        src = infeat; Csrc = 2;
        base = OFF_CLS + (long)p * 1024;
    } else if (p < 2112) {
        int t = p - 64;
        int local = t;
        ch = t & 63; t >>= 6;
        b  = t & 7;  t >>= 3;
        j  = t & 1;  t >>= 1;
        c  = t;
        src = feat; Csrc = CDA_;
        base = OFF_FEAT + (long)local * 1024;
    } else if (p < 2144) {
        int t = p - 2112;
        int local = t;
        ch = 0;
        b  = t & 7;  t >>= 3;
        j  = t & 1;  t >>= 1;
        c  = t;
        src = pesudo; Csrc = 1;
        base = OFF_PES + (long)local * 1024;
    } else {
        int t = p - 2144;
        int local = t;
        ch = 0;
        b  = t & 7;  t >>= 3;
        j  = t & 1;  t >>= 1;
        c  = t;
        src = labelT; Csrc = 1;
        base = OFF_TRUE + (long)local * 1024;
    }

    int sel = (b * 2 + c) * K_ + j;
    int px = g_selpx[sel];
    int py = g_selpy[sel];

    int dy  = t64 >> 1;            // 32 rows, 2 threads per row
    int dx0 = (t64 & 1) << 4;      // 16 consecutive floats each
    const float* sp = src + (((long)b * Csrc + ch) * H_ + py + dy) * H_ + px + dx0;

    float v[16];
#pragma unroll
    for (int i = 0; i < 16; i++) v[i] = sp[i];

    float* op = out + base + (long)t64 * 16;
#pragma unroll
    for (int q = 0; q < 4; q++)
        *reinterpret_cast<float4*>(op + q * 4) =
            make_float4(v[q * 4], v[q * 4 + 1], v[q * 4 + 2], v[q * 4 + 3]);
}

// ---------------------------------------------------------------------------
extern "C" void kernel_launch(void* const* d_in, const int* in_sizes, int n_in,
                              void* d_out, int out_size) {
    const float* infeat  = (const float*)d_in[0];
    const float* pesudo  = (const float*)d_in[1];
    const float* labelT  = (const float*)d_in[2];
    const float* featDA  = (const float*)d_in[3];
    float* out = (float*)d_out;

    dim3 g1(NBC_, NRB_);
    k_poolsel<<<g1, 256>>>(infeat, out);
    k_extract<<<544, 256>>>(infeat, pesudo, labelT, featDA, out);
}

// round 10
// speedup vs baseline: 1.4205x; 1.4205x over previous
#include <cuda_runtime.h>
#include <cuda_bf16.h>

// Problem constants
#define B_    8
#define H_    256
#define P_    225          // H - KER + 1
#define KER_  32
#define HALF_ 16
#define K_    2
#define CDA_  64
#define NBC_  16           // B * 2 classes
#define NRB_  15           // row-slabs per map
#define NCH_  8            // 32-col chunks per map row
#define NPART_ (NRB_ * NCH_)   // 120 partials per map

// Output section offsets (floats)
#define OFF_CLS   0
#define OFF_FEAT  65536
#define OFF_VALS  2162688
#define OFF_PES   2162720
#define OFF_TRUE  2195488
#define OFF_OXY   2228256

// Scratch — channel-0 maps only (p1 = 1 - p0 pointwise => pooled1 = 1 - pooled0)
__device__ float g_rowsum[B_ * H_ * P_];
__device__ float g_pooled[B_ * P_ * P_];
__device__ float g_cval0[B_ * NPART_];   // max of v        (channel 0)
__device__ int   g_cidx0[B_ * NPART_];
__device__ float g_cval1[B_ * NPART_];   // max of (1 - v)  (channel 1)
__device__ int   g_cidx1[B_ * NPART_];
__device__ int   g_selpx[NBC_ * K_];
__device__ int   g_selpy[NBC_ * K_];
__device__ unsigned g_tick[B_];          // per-map tickets (self-reset)

// Warp argmax combine: max value, lowest flat index on ties.
__device__ __forceinline__ void warp_argmax(float& bv, int& bix) {
#pragma unroll
    for (int o = 16; o > 0; o >>= 1) {
        float ov = __shfl_xor_sync(0xffffffffu, bv, o);
        int   oi = __shfl_xor_sync(0xffffffffu, bix, o);
        if (ov > bv || (ov == bv && oi < bix)) { bv = ov; bix = oi; }
    }
}

// ===========================================================================
// K1: channel-0 softmax prob + horizontal 32-window sums. One sigmoid, one
// chunk-scan per pixel. grid = B*H = 2048 blocks, 256 threads.
// ===========================================================================
__global__ void k_rowsum(const float* __restrict__ infeat) {
    int by = blockIdx.x;
    int b = by >> 8;
    int y = by & 255;
    int x = threadIdx.x;
    int lane = x & 31;

    __shared__ float sc[H_];

    float x0 = infeat[((b * 2 + 0) * H_ + y) * H_ + x];
    float x1 = infeat[((b * 2 + 1) * H_ + y) * H_ + x];
    float p = 1.0f / (1.0f + __expf(x1 - x0));   // p0 = e0/(e0+e1)

    float s = p;
#pragma unroll
    for (int o = 1; o < 32; o <<= 1) {
        float t = __shfl_up_sync(0xffffffffu, s, o);
        if (lane >= o) s += t;
    }
    sc[x] = s;
    __syncthreads();

    if (x < P_) {
        int w = x >> 5, r = x & 31;
        float S = sc[(w << 5) | 31];
        float win = (r == 0) ? S : (S - sc[x - 1]) + sc[x + 31];
        g_rowsum[(b * H_ + y) * P_ + x] = win;
    }
}

// ===========================================================================
// K2: vertical 32-window slide (15 rows/block) over channel-0 rowsums,
// dual argmax partials (v and 1-v); per-map ticket -> last slab block runs
// BOTH channels' greedy top-2 selections (128 threads each half).
// grid = (8 maps, 15 slabs), 256 threads.
// ===========================================================================
__global__ void __launch_bounds__(256)
k_poolsel(float* __restrict__ out) {
    __shared__ float sv[256];
    __shared__ int   si[256];
    __shared__ unsigned s_isLast;

    const int tid  = threadIdx.x;
    const int lane = tid & 31;
    const int warp = tid >> 5;
    const int m    = blockIdx.x;       // batch / map
    const int slab = blockIdx.y;       // 0..14
    const int y0   = slab * 15;

    const float* rs = g_rowsum + m * H_ * P_;
    float* outp = g_pooled + m * P_ * P_;

    float best0 = -1e30f, best1 = -1e30f;
    int bi0 = 0x7fffffff, bi1 = 0x7fffffff;

    if (tid < P_) {
        float s = 0.0f;
#pragma unroll
        for (int i = 0; i < KER_; i++) s += rs[(y0 + i) * P_ + tid];
        float v = s * (1.0f / 1024.0f);
        outp[y0 * P_ + tid] = v;
        best0 = v; bi0 = y0 * P_ + tid;
        best1 = 1.0f - v; bi1 = bi0;
#pragma unroll
        for (int q = 1; q < 15; q++) {
            int py = y0 + q;
            s += rs[(py + 31) * P_ + tid] - rs[(py - 1) * P_ + tid];
            v = s * (1.0f / 1024.0f);
            outp[py * P_ + tid] = v;
            int idx = py * P_ + tid;
            if (v > best0) { best0 = v; bi0 = idx; }
            float w = 1.0f - v;
            if (w > best1) { best1 = w; bi1 = idx; }
        }
    }
    warp_argmax(best0, bi0);
    warp_argmax(best1, bi1);
    if (lane == 0) {
        int o = (m * NRB_ + slab) * NCH_ + warp;
        g_cval0[o] = best0; g_cidx0[o] = bi0;
        g_cval1[o] = best1; g_cidx1[o] = bi1;
    }

    // ---- per-map ticket: last of 15 slab blocks does both selections ----
    __threadfence();
    __syncthreads();
    if (tid == 0) {
        unsigned t = atomicAdd(&g_tick[m], 1u);
        s_isLast = (t == NRB_ - 1) ? 1u : 0u;
    }
    __syncthreads();
    if (!s_isLast) return;
    __threadfence();

    const int half = tid >> 7;         // 0 -> channel 0, 1 -> channel 1
    const int h    = tid & 127;
    const int bc   = m * 2 + half;
    const int b    = m;
    const int c    = half;
    const float* pm = g_pooled + m * P_ * P_;
    const float* cval = half ? g_cval1 : g_cval0;
    const int*   cidx = half ? g_cidx1 : g_cidx0;

    // pass 1: reduce 120 partials (per half)
    float best = -1e30f;
    int bi = 0x7fffffff;
    if (h < NPART_) {
        best = cval[m * NPART_ + h];
        bi   = cidx[m * NPART_ + h];
    }
    sv[tid] = best; si[tid] = bi;
    __syncthreads();
    for (int s = 64; s > 0; s >>= 1) {
        if (h < s) {
            float ov = sv[tid + s];
            int   oi = si[tid + s];
            if (ov > sv[tid] || (ov == sv[tid] && oi < si[tid])) {
                sv[tid] = ov; si[tid] = oi;
            }
        }
        __syncthreads();
    }
    int idx0 = si[half << 7];
    float val0 = sv[half << 7];
    int py0 = idx0 / P_;
    int px0 = idx0 - py0 * P_;
    __syncthreads();

    // pass 2: untouched partials + MLP-batched rescan of touched cells
    int lo  = max(0, py0 - HALF_), hi  = min(P_, py0 + HALF_);
    int clo = max(0, px0 - HALF_), chi = min(P_, px0 + HALF_);
    int rblo = lo / 15, rbhi = (hi - 1) / 15;
    int cblo = clo / 32, cbhi = (chi - 1) / 32;

    best = -1e30f; bi = 0x7fffffff;
    if (h < NPART_) {
        int sb = h >> 3, cb = h & 7;
        if (sb < rblo || sb > rbhi || cb < cblo || cb > cbhi) {
            best = cval[m * NPART_ + h];
            bi   = cidx[m * NPART_ + h];
        }
    }
    int r0 = rblo * 15, r1 = min(P_, (rbhi + 1) * 15);
    int c0 = cblo * 32, c1 = min(P_, (cbhi + 1) * 32);
    int W = c1 - c0;
    int n = (r1 - r0) * W;                 // <= 3840
    for (int i0 = h; i0 < n; i0 += 128 * 8) {
#pragma unroll
        for (int u = 0; u < 8; u++) {
            int i = i0 + u * 128;
            if (i < n) {
                int rr = i / W;
                int col = c0 + (i - rr * W);
                int row = r0 + rr;
                int idx = row * P_ + col;
                float v = pm[idx];
                if (half) v = 1.0f - v;
                if (row >= lo && row < hi && col >= clo && col < chi) v = 0.0f;
                if (v > best || (v == best && idx < bi)) { best = v; bi = idx; }
            }
        }
    }
    sv[tid] = best; si[tid] = bi;
    __syncthreads();
    for (int s = 64; s > 0; s >>= 1) {
        if (h < s) {
            float ov = sv[tid + s];
            int   oi = si[tid + s];
            if (ov > sv[tid] || (ov == sv[tid] && oi < si[tid])) {
                sv[tid] = ov; si[tid] = oi;
            }
        }
        __syncthreads();
    }

    if (h == 0) {
        int idx1 = si[half << 7];
        float val1 = sv[half << 7];
        int py1 = idx1 / P_;
        int px1 = idx1 - py1 * P_;

        int pxs[K_] = {px0, px1};
        int pys[K_] = {py0, py1};
        float vals[K_] = {val0, val1};
#pragma unroll
        for (int j = 0; j < K_; j++) {
            g_selpx[bc * K_ + j] = pxs[j];
            g_selpy[bc * K_ + j] = pys[j];
            out[OFF_VALS + (c * K_ + j) * B_ + b] = vals[j];
            int o = OFF_OXY + ((c * K_ + j) * B_ + b) * 4;
            out[o + 0] = (float)pxs[j];
            out[o + 1] = (float)(pxs[j] + KER_ - 1);
            out[o + 2] = (float)pys[j];
            out[o + 3] = (float)(pys[j] + KER_ - 1);
        }
    }
    __syncthreads();
    if (tid == 0) g_tick[m] = 0;       // reset for next launch
}

// ===========================================================================
// K3: patch gather — exact R3 configuration (measured 8.1 us):
// 2176 blocks x 256 threads, 4 consecutive floats per thread.
// ===========================================================================
__global__ void k_extract(const float* __restrict__ infeat,
                          const float* __restrict__ pesudo,
                          const float* __restrict__ labelT,
                          const float* __restrict__ feat,
                          float* __restrict__ out) {
    int blk = blockIdx.x;
    const float* src;
    int Csrc, ch, c, j, b;
    long base;

    if (blk < 64) {
        int t = blk;
        ch = t & 1;  t >>= 1;
        b  = t & 7;  t >>= 3;
        j  = t & 1;  t >>= 1;
        c  = t;
        src = infeat; Csrc = 2;
        base = OFF_CLS + (long)blk * 1024;
    } else if (blk < 2112) {
        int t = blk - 64;
        int local = t;
        ch = t & 63; t >>= 6;
        b  = t & 7;  t >>= 3;
        j  = t & 1;  t >>= 1;
        c  = t;
        src = feat; Csrc = CDA_;
        base = OFF_FEAT + (long)local * 1024;
    } else if (blk < 2144) {
        int t = blk - 2112;
        int local = t;
        ch = 0;
        b  = t & 7;  t >>= 3;
        j  = t & 1;  t >>= 1;
        c  = t;
        src = pesudo; Csrc = 1;
        base = OFF_PES + (long)local * 1024;
    } else {
        int t = blk - 2144;
        int local = t;
        ch = 0;
        b  = t & 7;  t >>= 3;
        j  = t & 1;  t >>= 1;
        c  = t;
        src = labelT; Csrc = 1;
        base = OFF_TRUE + (long)local * 1024;
    }

    int sel = (b * 2 + c) * K_ + j;
    int px = g_selpx[sel];
    int py = g_selpy[sel];

    const float* s = src + (((long)b * Csrc + ch) * H_ + py) * H_ + px;

    int t = threadIdx.x;          // 256 threads, 4 consecutive floats each
    int dy = t >> 3;
    int dx = (t & 7) * 4;
    const float* sp = s + dy * H_ + dx;
    float4 v;
    v.x = sp[0]; v.y = sp[1]; v.z = sp[2]; v.w = sp[3];
    *reinterpret_cast<float4*>(out + base + (long)t * 4) = v;
}

// ---------------------------------------------------------------------------
extern "C" void kernel_launch(void* const* d_in, const int* in_sizes, int n_in,
                              void* d_out, int out_size) {
    const float* infeat  = (const float*)d_in[0];
    const float* pesudo  = (const float*)d_in[1];
    const float* labelT  = (const float*)d_in[2];
    const float* featDA  = (const float*)d_in[3];
    float* out = (float*)d_out;

    k_rowsum<<<B_ * H_, 256>>>(infeat);
    dim3 g2(B_, NRB_);
    k_poolsel<<<g2, 256>>>(out);
    k_extract<<<2176, 256>>>(infeat, pesudo, labelT, featDA, out);
}